// round 4
// baseline (speedup 1.0000x reference)
#include <cuda_runtime.h>
#include <cstdint>
#include <math.h>

// ============================================================================
// Problem constants (shapes are fixed by the reference)
// ============================================================================
#define NN     50000
#define EE     1600000
#define DD     128          // feature dim -> 32 float4 per row
#define NITER  20
#define NNEG   10
#define SPAN   49998u       // maxval - minval = 50000 - 2
#define MULT   39100u       // 2^32 % SPAN
#define BIGDEG 5000.0f

// ============================================================================
// Scratch (static device globals; no allocation allowed)
// ============================================================================
__device__ float g_repA[NN * DD];
__device__ float g_repB[NN * DD];
__device__ float g_mean[NN * DD];
__device__ float g_grad[NN * DD];
__device__ float g_deg[NN];
__device__ int   g_cnt[NN];
__device__ int   g_rowptr[NN + 1];
__device__ int   g_fill[NN];
__device__ int   g_esrc[EE];
__device__ float g_norm[NITER];

// ============================================================================
// Threefry-2x32 (20 rounds), matches jax._src.prng.threefry2x32
// (threefry_partitionable mode — verified exact in round 1, rel_err 3e-8)
// ============================================================================
__host__ __device__ __forceinline__ void tf2x32(uint32_t k0, uint32_t k1,
                                                uint32_t x0, uint32_t x1,
                                                uint32_t& o0, uint32_t& o1) {
    uint32_t ks2 = k0 ^ k1 ^ 0x1BD11BDAu;
    x0 += k0; x1 += k1;
#define TF_R(r) { x0 += x1; x1 = (x1 << (r)) | (x1 >> (32 - (r))); x1 ^= x0; }
    TF_R(13) TF_R(15) TF_R(26) TF_R(6)   x0 += k1;  x1 += ks2 + 1u;
    TF_R(17) TF_R(29) TF_R(16) TF_R(24)  x0 += ks2; x1 += k0  + 2u;
    TF_R(13) TF_R(15) TF_R(26) TF_R(6)   x0 += k0;  x1 += k1  + 3u;
    TF_R(17) TF_R(29) TF_R(16) TF_R(24)  x0 += k1;  x1 += ks2 + 4u;
    TF_R(13) TF_R(15) TF_R(26) TF_R(6)   x0 += ks2; x1 += k0  + 5u;
#undef TF_R
    o0 = x0; o1 = x1;
}

__device__ __forceinline__ uint32_t rbits32(uint32_t kx, uint32_t ky, uint32_t e) {
    uint32_t a, b;
    tf2x32(kx, ky, 0u, e, a, b);
    return a ^ b;
}

// ============================================================================
// Build kernels (run once per launch)
// ============================================================================
__global__ void k_zero() {
    int i = blockIdx.x * blockDim.x + threadIdx.x;
    if (i < NN)    g_cnt[i] = 0;
    if (i < NITER) g_norm[i] = 0.0f;
}

__global__ void k_hist(const int* __restrict__ dst) {
    int i = blockIdx.x * blockDim.x + threadIdx.x;
    if (i < EE) atomicAdd(&g_cnt[dst[i]], 1);
}

// Single-block scan: 1024 threads, each owns a contiguous chunk.
__global__ void k_scan() {
    __shared__ int sh[1024];
    const int t = threadIdx.x;
    const int CH = (NN + 1023) / 1024;  // 49
    const int base = t * CH;
    int s = 0;
    for (int j = 0; j < CH; j++) {
        int idx = base + j;
        if (idx < NN) s += g_cnt[idx];
    }
    sh[t] = s;
    __syncthreads();
    for (int off = 1; off < 1024; off <<= 1) {
        int v = (t >= off) ? sh[t - off] : 0;
        __syncthreads();
        sh[t] += v;
        __syncthreads();
    }
    int run = (t == 0) ? 0 : sh[t - 1];
    for (int j = 0; j < CH; j++) {
        int idx = base + j;
        if (idx < NN) {
            int c = g_cnt[idx];
            g_rowptr[idx] = run;
            g_fill[idx]   = run;
            g_deg[idx]    = (float)c;
            run += c;
        }
    }
    if (t == 1023) g_rowptr[NN] = run;  // == EE
}

__global__ void k_scatter(const int* __restrict__ src, const int* __restrict__ dst) {
    int i = blockIdx.x * blockDim.x + threadIdx.x;
    if (i < EE) {
        int p = atomicAdd(&g_fill[dst[i]], 1);
        g_esrc[p] = src[i];
    }
}

__global__ void k_copy(const float4* __restrict__ in) {
    int i = blockIdx.x * blockDim.x + threadIdx.x;
    if (i < NN * (DD / 4)) reinterpret_cast<float4*>(g_repA)[i] = in[i];
}

// ============================================================================
// Fused iteration kernel. One warp per node, 8 nodes/block (6250 blocks).
// Latency-oriented: neg gathers hoisted before the mailbox loop; one
// interleaved 11-way butterfly reduction; 32-deep MLP in the mailbox loop.
// ============================================================================
__global__ void __launch_bounds__(256)
k_meangrad(const float* __restrict__ rep_, int t,
           uint32_t k1x, uint32_t k1y, uint32_t k2x, uint32_t k2y) {
    const float4* rep = reinterpret_cast<const float4*>(rep_);
    const int warp = threadIdx.x >> 5;          // 0..7
    const int w    = blockIdx.x * 8 + warp;     // node id (6250*8=50000 exact)
    const int lane = threadIdx.x & 31;
    __shared__ float sh_ss[8];

    // ---- negative indices (pure ALU, no memory) ----
    int idx = 0;
    if (lane < NNEG) {
        uint32_t el = (uint32_t)w * NNEG + (uint32_t)lane;
        uint32_t hi = rbits32(k1x, k1y, el);
        uint32_t lo = rbits32(k2x, k2y, el);
        uint32_t off = ((hi % SPAN) * MULT + (lo % SPAN)) % SPAN;
        idx = 2 + (int)off;
    }

    // ---- issue self-row + all 10 negative gathers up-front; they stay in
    //      flight / registers across the whole mailbox loop ----
    float4 r = rep[w * 32 + lane];
    float4 v[NNEG];
#pragma unroll
    for (int j = 0; j < NNEG; j++) {
        int ij = __shfl_sync(0xffffffffu, idx, j);
        v[j] = rep[ij * 32 + lane];
    }

    // ---- mailbox mean: lane-cooperative index staging, up to 32 gathers in
    //      flight per warp ----
    const int s = g_rowptr[w], e = g_rowptr[w + 1];
    float4 acc = make_float4(0.f, 0.f, 0.f, 0.f);
    for (int base = s; base < e; base += 32) {
        const int n = e - base;                 // >=1
        int my = 0;
        if (base + lane < e) my = g_esrc[base + lane];
#pragma unroll
        for (int j = 0; j < 32; j++) {
            int sidx = __shfl_sync(0xffffffffu, my, j);
            if (j < n) {
                float4 a = rep[sidx * 32 + lane];
                acc.x += a.x; acc.y += a.y; acc.z += a.z; acc.w += a.w;
            }
        }
    }
    const float dg   = g_deg[w];
    const float dinv = 1.0f / fmaxf(dg, 1.0f);
    float4 m = make_float4(acc.x * dinv, acc.y * dinv, acc.z * dinv, acc.w * dinv);
    reinterpret_cast<float4*>(g_mean)[w * 32 + lane] = m;

    // ---- all 11 dot-product partials, ONE interleaved butterfly (ILP=11) ----
    float p[NNEG + 1];
    p[0] = r.x * m.x + r.y * m.y + r.z * m.z + r.w * m.w;
#pragma unroll
    for (int j = 0; j < NNEG; j++)
        p[j + 1] = r.x * v[j].x + r.y * v[j].y + r.z * v[j].z + r.w * v[j].w;
#pragma unroll
    for (int o = 16; o > 0; o >>= 1) {
#pragma unroll
        for (int j = 0; j < NNEG + 1; j++)
            p[j] += __shfl_xor_sync(0xffffffffu, p[j], o);
    }

    // ---- softmax over 11 logits ----
    float mx = p[0];
#pragma unroll
    for (int j = 1; j < NNEG + 1; j++) mx = fmaxf(mx, p[j]);
    float Z = 0.0f;
#pragma unroll
    for (int j = 0; j < NNEG + 1; j++) { p[j] = expf(p[j] - mx); Z += p[j]; }
    float inv = 1.0f / Z;
    float p0  = p[0] * inv;

    float4 g = make_float4((p0 - 1.0f) * m.x, (p0 - 1.0f) * m.y,
                           (p0 - 1.0f) * m.z, (p0 - 1.0f) * m.w);
#pragma unroll
    for (int j = 0; j < NNEG; j++) {
        float pj = p[j + 1] * inv;
        g.x += pj * v[j].x; g.y += pj * v[j].y; g.z += pj * v[j].z; g.w += pj * v[j].w;
    }

    bool eligible = (dg >= 2.0f) && (dg <= BIGDEG);
    if (!eligible) g = make_float4(0.f, 0.f, 0.f, 0.f);

    reinterpret_cast<float4*>(g_grad)[w * 32 + lane] = g;

    // ---- grad-norm: warp reduce -> smem -> ONE atomic per block ----
    float ss = g.x * g.x + g.y * g.y + g.z * g.z + g.w * g.w;
#pragma unroll
    for (int o = 16; o > 0; o >>= 1) ss += __shfl_xor_sync(0xffffffffu, ss, o);
    if (lane == 0) sh_ss[warp] = ss;
    __syncthreads();
    if (threadIdx.x == 0) {
        float bs = sh_ss[0] + sh_ss[1] + sh_ss[2] + sh_ss[3]
                 + sh_ss[4] + sh_ss[5] + sh_ss[6] + sh_ss[7];
        if (bs != 0.0f) atomicAdd(&g_norm[t], bs);
    }
}

// ============================================================================
// Update kernel: clipped SGD (+ big-degree mean-pool branch)
// ============================================================================
__global__ void k_update(const float* __restrict__ rep_, float* __restrict__ out_, int t) {
    const int i = blockIdx.x * blockDim.x + threadIdx.x;  // over NN*32 float4s
    if (i >= NN * (DD / 4)) return;
    float S = g_norm[t];
    float coef = fminf(1.0f, 2.0f / (sqrtf(S) + 1e-6f));
    int node = i >> 5;
    float4 res;
    if (g_deg[node] > BIGDEG) {
        res = reinterpret_cast<const float4*>(g_mean)[i];
    } else {
        float4 r = reinterpret_cast<const float4*>(rep_)[i];
        float4 g = reinterpret_cast<const float4*>(g_grad)[i];
        res = make_float4(r.x - coef * g.x, r.y - coef * g.y,
                          r.z - coef * g.z, r.w - coef * g.w);
    }
    reinterpret_cast<float4*>(out_)[i] = res;
}

// ============================================================================
// Host: JAX key derivation (split(key(1),20) -> per-iter randint subkeys)
// ============================================================================
static void derive_keys(uint32_t* k1x, uint32_t* k1y, uint32_t* k2x, uint32_t* k2y) {
    uint32_t kt0[NITER], kt1[NITER];
    for (int t = 0; t < NITER; t++)
        tf2x32(0u, 1u, 0u, (uint32_t)t, kt0[t], kt1[t]);
    for (int t = 0; t < NITER; t++) {
        tf2x32(kt0[t], kt1[t], 0u, 0u, k1x[t], k1y[t]);
        tf2x32(kt0[t], kt1[t], 0u, 1u, k2x[t], k2y[t]);
    }
}

// ============================================================================
// Entry point
// ============================================================================
extern "C" void kernel_launch(void* const* d_in, const int* in_sizes, int n_in,
                              void* d_out, int out_size) {
    const float* repre = (const float*)d_in[0];
    const int*   src   = (const int*)d_in[1];
    const int*   dst   = (const int*)d_in[2];
    float*       out   = (float*)d_out;

    float *repA, *repB;
    cudaGetSymbolAddress((void**)&repA, g_repA);
    cudaGetSymbolAddress((void**)&repB, g_repB);

    uint32_t k1x[NITER], k1y[NITER], k2x[NITER], k2y[NITER];
    derive_keys(k1x, k1y, k2x, k2y);

    const int TB = 256;
    // ---- build phase (once per launch, amortized over 20 iterations) ----
    k_zero<<<(NN + TB - 1) / TB, TB>>>();
    k_hist<<<(EE + TB - 1) / TB, TB>>>(dst);
    k_scan<<<1, 1024>>>();
    k_scatter<<<(EE + TB - 1) / TB, TB>>>(src, dst);
    k_copy<<<(NN * (DD / 4) + TB - 1) / TB, TB>>>((const float4*)repre);

    // ---- 20 iterations, ping-pong buffers, final iter writes d_out ----
    float* cur = repA;
    for (int t = 0; t < NITER; t++) {
        k_meangrad<<<NN / 8, 256>>>(cur, t, k1x[t], k1y[t], k2x[t], k2y[t]);
        float* nxt = (t == NITER - 1) ? out : ((cur == repA) ? repB : repA);
        k_update<<<(NN * (DD / 4) + TB - 1) / TB, TB>>>(cur, nxt, t);
        cur = nxt;
    }
}

// round 5
// speedup vs baseline: 1.4570x; 1.4570x over previous
#include <cuda_runtime.h>
#include <cuda_bf16.h>
#include <cstdint>
#include <math.h>

// ============================================================================
// Problem constants
// ============================================================================
#define NN     50000
#define EE     1600000
#define DD     128          // feature dim -> 32 float4 per row
#define NITER  20
#define NNEG   10
#define SPAN   49998u
#define MULT   39100u       // 2^32 % SPAN
#define BIGDEG 5000.0f

// ============================================================================
// Scratch (static device globals). Working set kept << L2 capacity:
// rep lives in d_out (25.6MB), gradH is bf16 (12.8MB), esrc 6.4MB.
// ============================================================================
__device__ __nv_bfloat16 g_gradH[NN * DD];  // grad (or mean, for big-deg nodes)
__device__ float g_deg[NN];
__device__ int   g_cnt[NN];                 // statically zero-init; re-zeroed by k_scan
__device__ int   g_rowptr[NN + 1];
__device__ int   g_fill[NN];
__device__ int   g_esrc[EE];
__device__ float g_norm[NITER];

// ============================================================================
// Threefry-2x32 (threefry_partitionable — verified exact, rel_err 3e-8)
// ============================================================================
__host__ __device__ __forceinline__ void tf2x32(uint32_t k0, uint32_t k1,
                                                uint32_t x0, uint32_t x1,
                                                uint32_t& o0, uint32_t& o1) {
    uint32_t ks2 = k0 ^ k1 ^ 0x1BD11BDAu;
    x0 += k0; x1 += k1;
#define TF_R(r) { x0 += x1; x1 = (x1 << (r)) | (x1 >> (32 - (r))); x1 ^= x0; }
    TF_R(13) TF_R(15) TF_R(26) TF_R(6)   x0 += k1;  x1 += ks2 + 1u;
    TF_R(17) TF_R(29) TF_R(16) TF_R(24)  x0 += ks2; x1 += k0  + 2u;
    TF_R(13) TF_R(15) TF_R(26) TF_R(6)   x0 += k0;  x1 += k1  + 3u;
    TF_R(17) TF_R(29) TF_R(16) TF_R(24)  x0 += k1;  x1 += ks2 + 4u;
    TF_R(13) TF_R(15) TF_R(26) TF_R(6)   x0 += ks2; x1 += k0  + 5u;
#undef TF_R
    o0 = x0; o1 = x1;
}

__device__ __forceinline__ uint32_t rbits32(uint32_t kx, uint32_t ky, uint32_t e) {
    uint32_t a, b;
    tf2x32(kx, ky, 0u, e, a, b);
    return a ^ b;
}

// ============================================================================
// Build kernels (4 launches per call)
// ============================================================================
__global__ void k_hist(const int* __restrict__ dst) {
    int i = blockIdx.x * blockDim.x + threadIdx.x;
    if (i < EE) atomicAdd(&g_cnt[dst[i]], 1);
}

// Single-block scan. Also re-zeros g_cnt (for the next graph replay) and g_norm.
__global__ void k_scan() {
    __shared__ int sh[1024];
    const int t = threadIdx.x;
    const int CH = (NN + 1023) / 1024;  // 49
    const int base = t * CH;
    if (t < NITER) g_norm[t] = 0.0f;
    int s = 0;
    int loc[CH];
    for (int j = 0; j < CH; j++) {
        int idx = base + j;
        loc[j] = (idx < NN) ? g_cnt[idx] : 0;
        s += loc[j];
    }
    sh[t] = s;
    __syncthreads();
    for (int off = 1; off < 1024; off <<= 1) {
        int v = (t >= off) ? sh[t - off] : 0;
        __syncthreads();
        sh[t] += v;
        __syncthreads();
    }
    int run = (t == 0) ? 0 : sh[t - 1];
    for (int j = 0; j < CH; j++) {
        int idx = base + j;
        if (idx < NN) {
            int c = loc[j];
            g_rowptr[idx] = run;
            g_fill[idx]   = run;
            g_deg[idx]    = (float)c;
            g_cnt[idx]    = 0;        // ready for next replay
            run += c;
        }
    }
    if (t == 1023) g_rowptr[NN] = run;  // == EE
}

__global__ void k_scatter(const int* __restrict__ src, const int* __restrict__ dst) {
    int i = blockIdx.x * blockDim.x + threadIdx.x;
    if (i < EE) {
        int p = atomicAdd(&g_fill[dst[i]], 1);
        g_esrc[p] = src[i];
    }
}

// rep table lives in d_out from here on
__global__ void k_copy(const float4* __restrict__ in, float4* __restrict__ out) {
    int i = blockIdx.x * blockDim.x + threadIdx.x;
    if (i < NN * (DD / 4)) out[i] = in[i];
}

// ============================================================================
// Fused iteration kernel. One warp per node, 8 nodes/block (6250 blocks).
// Round-2 proven structure: unroll-8 direct index loads; negatives gathered in
// the grad phase; interleaved 11-way butterfly reduction; bf16 grad/mean store.
// ============================================================================
__global__ void __launch_bounds__(256, 2)
k_meangrad(const float* __restrict__ rep_, int t,
           uint32_t k1x, uint32_t k1y, uint32_t k2x, uint32_t k2y) {
    const float4* rep = reinterpret_cast<const float4*>(rep_);
    const int warp = threadIdx.x >> 5;          // 0..7
    const int w    = blockIdx.x * 8 + warp;     // node id (6250*8=50000 exact)
    const int lane = threadIdx.x & 31;
    __shared__ float sh_ss[8];

    // ---- mailbox mean (CSR segmented sum, unroll 8 for MLP) ----
    const int s = g_rowptr[w], e = g_rowptr[w + 1];
    float4 acc = make_float4(0.f, 0.f, 0.f, 0.f);
    int i = s;
    for (; i + 8 <= e; i += 8) {
        int s0 = g_esrc[i],     s1 = g_esrc[i + 1], s2 = g_esrc[i + 2], s3 = g_esrc[i + 3];
        int s4 = g_esrc[i + 4], s5 = g_esrc[i + 5], s6 = g_esrc[i + 6], s7 = g_esrc[i + 7];
        float4 a  = rep[s0 * 32 + lane];
        float4 b  = rep[s1 * 32 + lane];
        float4 c  = rep[s2 * 32 + lane];
        float4 d  = rep[s3 * 32 + lane];
        float4 a2 = rep[s4 * 32 + lane];
        float4 b2 = rep[s5 * 32 + lane];
        float4 c2 = rep[s6 * 32 + lane];
        float4 d2 = rep[s7 * 32 + lane];
        acc.x += ((a.x + b.x) + (c.x + d.x)) + ((a2.x + b2.x) + (c2.x + d2.x));
        acc.y += ((a.y + b.y) + (c.y + d.y)) + ((a2.y + b2.y) + (c2.y + d2.y));
        acc.z += ((a.z + b.z) + (c.z + d.z)) + ((a2.z + b2.z) + (c2.z + d2.z));
        acc.w += ((a.w + b.w) + (c.w + d.w)) + ((a2.w + b2.w) + (c2.w + d2.w));
    }
    for (; i < e; ++i) {
        float4 a = rep[g_esrc[i] * 32 + lane];
        acc.x += a.x; acc.y += a.y; acc.z += a.z; acc.w += a.w;
    }
    const float dg   = g_deg[w];
    const float dinv = 1.0f / fmaxf(dg, 1.0f);
    float4 m = make_float4(acc.x * dinv, acc.y * dinv, acc.z * dinv, acc.w * dinv);

    // ---- contrastive grad ----
    float4 r = rep[w * 32 + lane];

    int idx = 0;
    if (lane < NNEG) {
        uint32_t el = (uint32_t)w * NNEG + (uint32_t)lane;
        uint32_t hi = rbits32(k1x, k1y, el);
        uint32_t lo = rbits32(k2x, k2y, el);
        uint32_t off = ((hi % SPAN) * MULT + (lo % SPAN)) % SPAN;
        idx = 2 + (int)off;
    }

    float4 v[NNEG];
    float  p[NNEG + 1];
    p[0] = r.x * m.x + r.y * m.y + r.z * m.z + r.w * m.w;
#pragma unroll
    for (int j = 0; j < NNEG; j++) {
        int ij = __shfl_sync(0xffffffffu, idx, j);
        v[j] = rep[ij * 32 + lane];
        p[j + 1] = r.x * v[j].x + r.y * v[j].y + r.z * v[j].z + r.w * v[j].w;
    }
    // one interleaved butterfly for all 11 partials (ILP=11)
#pragma unroll
    for (int o = 16; o > 0; o >>= 1) {
#pragma unroll
        for (int j = 0; j < NNEG + 1; j++)
            p[j] += __shfl_xor_sync(0xffffffffu, p[j], o);
    }

    float mx = p[0];
#pragma unroll
    for (int j = 1; j < NNEG + 1; j++) mx = fmaxf(mx, p[j]);
    float Z = 0.0f;
#pragma unroll
    for (int j = 0; j < NNEG + 1; j++) { p[j] = expf(p[j] - mx); Z += p[j]; }
    float inv = 1.0f / Z;
    float p0  = p[0] * inv;

    float4 g = make_float4((p0 - 1.0f) * m.x, (p0 - 1.0f) * m.y,
                           (p0 - 1.0f) * m.z, (p0 - 1.0f) * m.w);
#pragma unroll
    for (int j = 0; j < NNEG; j++) {
        float pj = p[j + 1] * inv;
        g.x += pj * v[j].x; g.y += pj * v[j].y; g.z += pj * v[j].z; g.w += pj * v[j].w;
    }

    bool eligible = (dg >= 2.0f) && (dg <= BIGDEG);
    if (!eligible) g = make_float4(0.f, 0.f, 0.f, 0.f);
    bool big = (dg > BIGDEG);

    // store bf16: grad for normal nodes, mean for big-degree nodes
    float4 st = big ? m : g;
    __nv_bfloat162 lo2 = __floats2bfloat162_rn(st.x, st.y);
    __nv_bfloat162 hi2 = __floats2bfloat162_rn(st.z, st.w);
    uint2 q;
    q.x = *reinterpret_cast<uint32_t*>(&lo2);
    q.y = *reinterpret_cast<uint32_t*>(&hi2);
    reinterpret_cast<uint2*>(g_gradH)[w * 32 + lane] = q;

    // ---- grad-norm from fp32 grads: warp reduce -> smem -> 1 atomic/block ----
    float ss = g.x * g.x + g.y * g.y + g.z * g.z + g.w * g.w;
#pragma unroll
    for (int o = 16; o > 0; o >>= 1) ss += __shfl_xor_sync(0xffffffffu, ss, o);
    if (lane == 0) sh_ss[warp] = ss;
    __syncthreads();
    if (threadIdx.x == 0) {
        float bs = sh_ss[0] + sh_ss[1] + sh_ss[2] + sh_ss[3]
                 + sh_ss[4] + sh_ss[5] + sh_ss[6] + sh_ss[7];
        if (bs != 0.0f) atomicAdd(&g_norm[t], bs);
    }
}

// ============================================================================
// Update kernel: clipped SGD in-place on the rep table (d_out).
// big-degree nodes: gradH slot holds the mean -> take it directly.
// ============================================================================
__global__ void k_update(float* __restrict__ rep_, int t) {
    const int i = blockIdx.x * blockDim.x + threadIdx.x;  // over NN*32 float4s
    if (i >= NN * (DD / 4)) return;
    float S = g_norm[t];
    float coef = fminf(1.0f, 2.0f / (sqrtf(S) + 1e-6f));
    int node = i >> 5;

    uint2 q = reinterpret_cast<const uint2*>(g_gradH)[i];
    __nv_bfloat162 lo2 = *reinterpret_cast<__nv_bfloat162*>(&q.x);
    __nv_bfloat162 hi2 = *reinterpret_cast<__nv_bfloat162*>(&q.y);
    float2 hl = __bfloat1622float2(lo2);
    float2 hh = __bfloat1622float2(hi2);

    float4 res;
    if (g_deg[node] > BIGDEG) {
        res = make_float4(hl.x, hl.y, hh.x, hh.y);       // mean-pool branch
    } else {
        float4 r = reinterpret_cast<const float4*>(rep_)[i];
        res = make_float4(r.x - coef * hl.x, r.y - coef * hl.y,
                          r.z - coef * hh.x, r.w - coef * hh.y);
    }
    reinterpret_cast<float4*>(rep_)[i] = res;
}

// ============================================================================
// Host: JAX key derivation
// ============================================================================
static void derive_keys(uint32_t* k1x, uint32_t* k1y, uint32_t* k2x, uint32_t* k2y) {
    uint32_t kt0[NITER], kt1[NITER];
    for (int t = 0; t < NITER; t++)
        tf2x32(0u, 1u, 0u, (uint32_t)t, kt0[t], kt1[t]);
    for (int t = 0; t < NITER; t++) {
        tf2x32(kt0[t], kt1[t], 0u, 0u, k1x[t], k1y[t]);
        tf2x32(kt0[t], kt1[t], 0u, 1u, k2x[t], k2y[t]);
    }
}

// ============================================================================
// Entry point
// ============================================================================
extern "C" void kernel_launch(void* const* d_in, const int* in_sizes, int n_in,
                              void* d_out, int out_size) {
    const float* repre = (const float*)d_in[0];
    const int*   src   = (const int*)d_in[1];
    const int*   dst   = (const int*)d_in[2];
    float*       out   = (float*)d_out;

    uint32_t k1x[NITER], k1y[NITER], k2x[NITER], k2y[NITER];
    derive_keys(k1x, k1y, k2x, k2y);

    const int TB = 256;
    // ---- build phase: 4 launches (g_cnt re-zeroed inside k_scan) ----
    k_hist<<<(EE + TB - 1) / TB, TB>>>(dst);
    k_scan<<<1, 1024>>>();
    k_scatter<<<(EE + TB - 1) / TB, TB>>>(src, dst);
    k_copy<<<(NN * (DD / 4) + TB - 1) / TB, TB>>>((const float4*)repre, (float4*)out);

    // ---- 20 iterations, in-place on d_out ----
    for (int t = 0; t < NITER; t++) {
        k_meangrad<<<NN / 8, 256>>>(out, t, k1x[t], k1y[t], k2x[t], k2y[t]);
        k_update<<<(NN * (DD / 4) + TB - 1) / TB, TB>>>(out, t);
    }
}